// round 12
// baseline (speedup 1.0000x reference)
#include <cuda_runtime.h>
#include <cuda_fp16.h>
#include <cstdint>

#define BSZ 4096
#define DIM 128
#define NT  32   // 4096 / 128 tiles per dimension
#define N_AB   (NT * NT)            // 1024 full ab tiles
#define N_TRI  (NT * (NT + 1) / 2)  // 528 upper-triangle tiles
#define N_TILES (N_AB + 2 * N_TRI)  // 2080

// ---------------- scratch (device globals; no runtime allocation) -----------
__device__ __align__(256) __half g_Zi_h[BSZ * DIM];   // fp16 normalized rows (links[:,0])
__device__ __align__(256) __half g_Zj_h[BSZ * DIM];   // fp16 normalized rows (links[:,1])
__device__ float g_sa[BSZ];     // sum exp(logit-20) rows of logits_a
__device__ float g_sb[BSZ];     // sum exp(logit-20) rows of logits_b
__device__ float g_diag[BSZ];   // logits_ab[i,i] (exact fp32)

__device__ __forceinline__ float ex2f(float x) {
    float y;
    asm("ex2.approx.ftz.f32 %0, %1;" : "=f"(y) : "f"(x));
    return y;
}

__device__ __forceinline__ uint32_t smem_u32(const void* p) {
    uint32_t a;
    asm("{ .reg .u64 t; cvta.to.shared.u64 t, %1; cvt.u32.u64 %0, t; }" : "=r"(a) : "l"(p));
    return a;
}

__device__ __forceinline__ void cp16(uint32_t dst, const void* src) {
    asm volatile("cp.async.cg.shared.global [%0], [%1], 16;" :: "r"(dst), "l"(src) : "memory");
}
#define CP_COMMIT() asm volatile("cp.async.commit_group;" ::: "memory")
#define CP_WAIT(n)  asm volatile("cp.async.wait_group %0;" :: "n"(n) : "memory")

__device__ __forceinline__ void ldm4(uint32_t* r, uint32_t addr) {
    asm volatile("ldmatrix.sync.aligned.m8n8.x4.shared.b16 {%0,%1,%2,%3}, [%4];"
                 : "=r"(r[0]), "=r"(r[1]), "=r"(r[2]), "=r"(r[3]) : "r"(addr));
}

__device__ __forceinline__ void mma_f16(float* d, const uint32_t* a, const uint32_t* b) {
    asm volatile("mma.sync.aligned.m16n8k16.row.col.f32.f16.f16.f32 "
                 "{%0,%1,%2,%3}, {%4,%5,%6,%7}, {%8,%9}, {%0,%1,%2,%3};"
                 : "+f"(d[0]), "+f"(d[1]), "+f"(d[2]), "+f"(d[3])
                 : "r"(a[0]), "r"(a[1]), "r"(a[2]), "r"(a[3]), "r"(b[0]), "r"(b[1]));
}

// ---------------- kernel 1: gather + normalize + fp16 store + exact diag ----
// One warp per link row; each thread loads Zi and Zj chunks (MLP=2), three
// shfl reductions give both norms and the exact diag dot. No smem.
__global__ void gather_norm(const float* __restrict__ emb,
                            const int* __restrict__ links32,
                            float* __restrict__ out) {
    int tid  = blockIdx.x * blockDim.x + threadIdx.x;
    if (tid < BSZ) { g_sa[tid] = 0.f; g_sb[tid] = 0.f; }
    if (tid == 0) out[0] = 0.f;      // accumulated by finalize_partial

    int lane = threadIdx.x & 31;
    int row  = tid >> 5;             // link row 0..4095 (grid = 512 x 256)

    // dtype sniff: int64 links have all-zero odd 32-bit words (values < 2e5)
    bool is64 = true;
#pragma unroll
    for (int j = 0; j < 16; j++) is64 &= (__ldg(&links32[2 * j + 1]) == 0);

    long long si, sj;
    if (is64) {
        si = reinterpret_cast<const long long*>(links32)[2 * row];
        sj = reinterpret_cast<const long long*>(links32)[2 * row + 1];
    } else {
        si = (long long)links32[2 * row];
        sj = (long long)links32[2 * row + 1];
    }

    float4 a = reinterpret_cast<const float4*>(emb + (size_t)si * DIM)[lane];
    float4 b = reinterpret_cast<const float4*>(emb + (size_t)sj * DIM)[lane];

    float ssA = a.x * a.x + a.y * a.y + a.z * a.z + a.w * a.w;
    float ssB = b.x * b.x + b.y * b.y + b.z * b.z + b.w * b.w;
    float dab = a.x * b.x + a.y * b.y + a.z * b.z + a.w * b.w;
#pragma unroll
    for (int o = 16; o; o >>= 1) {
        ssA += __shfl_xor_sync(0xffffffffu, ssA, o);
        ssB += __shfl_xor_sync(0xffffffffu, ssB, o);
        dab += __shfl_xor_sync(0xffffffffu, dab, o);
    }
    float invA = 1.0f / fmaxf(sqrtf(ssA), 1e-12f);
    float invB = 1.0f / fmaxf(sqrtf(ssB), 1e-12f);

    __half2 ha0; ha0.x = __float2half_rn(a.x * invA); ha0.y = __float2half_rn(a.y * invA);
    __half2 ha1; ha1.x = __float2half_rn(a.z * invA); ha1.y = __float2half_rn(a.w * invA);
    __half2 hb0; hb0.x = __float2half_rn(b.x * invB); hb0.y = __float2half_rn(b.y * invB);
    __half2 hb1; hb1.x = __float2half_rn(b.z * invB); hb1.y = __float2half_rn(b.w * invB);
    __half* di = g_Zi_h + row * DIM + lane * 4;
    __half* dj = g_Zj_h + row * DIM + lane * 4;
    reinterpret_cast<__half2*>(di)[0] = ha0;
    reinterpret_cast<__half2*>(di)[1] = ha1;
    reinterpret_cast<__half2*>(dj)[0] = hb0;
    reinterpret_cast<__half2*>(dj)[1] = hb1;

    if (lane == 0) g_diag[row] = dab * invA * invB * 20.0f;
}

// ---------------- kernel 2: fp16 mma.sync Gram tile + fused epilogue --------
// 256 threads = 8 warps in a 4x2 grid; warp tile 32 rows x 64 cols.
// smem: 2 tiles [A | B], 128 rows x 128 fp16, rows padded to 272B.
// Tile loads split into FOUR cp.async K-quarter groups: only the first
// quarter's latency is exposed; the rest streams under MMA.
#define PB    272            // bytes per smem row
#define BUFB  (128 * PB)     // 34816 bytes per buffer
#define SMEM_DYN (2 * BUFB)  // 69632

__global__ __launch_bounds__(256, 2) void tile_kernel() {
    // Dense tile id -> (type, ti, tj). [0,1024): ab full; then two triangles.
    int bid = blockIdx.x;
    int type, ti, tj;
    if (bid < N_AB) {
        type = 0; ti = bid >> 5; tj = bid & 31;
    } else {
        int idx = bid - N_AB;
        type = 1 + (idx >= N_TRI);
        if (idx >= N_TRI) idx -= N_TRI;
        int i = (int)((65.0f - sqrtf(4225.0f - 8.0f * (float)idx)) * 0.5f);
        while (i > 0 && (i * NT - i * (i - 1) / 2) > idx) i--;
        while ((i + 1) * NT - (i + 1) * i / 2 <= idx) i++;
        ti = i;
        tj = i + (idx - (i * NT - i * (i - 1) / 2));
    }

    extern __shared__ char smem[];
    __shared__ float red_r[2][128];
    __shared__ float red_c[4][128];

    const __half *A_g, *B_g;
    A_g = (type == 2) ? g_Zj_h : g_Zi_h;
    B_g = (type == 0) ? g_Zj_h : A_g;

    const int ib = ti * 128, jb = tj * 128;
    const uint32_t sb = smem_u32(smem);
    int t = threadIdx.x;
    int wid = t >> 5, lid = t & 31;
    int wy = wid & 3, wx = wid >> 2;   // warp tile: rows wy*32..+32, cols wx*64..+64

    // ---- K-quarter cp.async loads: group h covers ch 4h..4h+3 (ks 2h,2h+1) -
#pragma unroll
    for (int h = 0; h < 4; h++) {
#pragma unroll
        for (int i = 0; i < 2; i++) {
            int idx = t + 256 * i;          // 0..511 per quarter
            int row = idx >> 2, chh = idx & 3;
            int ch  = h * 4 + chh;
            uint32_t doff = (uint32_t)(row * PB + ch * 16);
            cp16(sb + doff,        A_g + (size_t)(ib + row) * DIM + ch * 8);
            cp16(sb + BUFB + doff, B_g + (size_t)(jb + row) * DIM + ch * 8);
        }
        CP_COMMIT();
    }

    // ---- ldmatrix base addresses (k-invariant parts) ----
    int rowA = lid & 15, ca = lid >> 4;
    int rowB = (lid & 7) | ((lid >> 1) & 8);
    int cb   = (lid >> 3) & 1;

    uint32_t aBase[2], bBase[4];
#pragma unroll
    for (int mt = 0; mt < 2; mt++)
        aBase[mt] = sb + (uint32_t)((wy * 32 + mt * 16 + rowA) * PB + ca * 16);
#pragma unroll
    for (int n16 = 0; n16 < 4; n16++)
        bBase[n16] = sb + BUFB + (uint32_t)((wx * 64 + n16 * 16 + rowB) * PB + cb * 16);

    float acc[2][8][4];
#pragma unroll
    for (int mt = 0; mt < 2; mt++)
#pragma unroll
        for (int nt = 0; nt < 8; nt++)
#pragma unroll
            for (int r = 0; r < 4; r++) acc[mt][nt][r] = 0.f;

#define KSTEP(ks)                                                              \
    do {                                                                       \
        uint32_t a_[2][4], b_[4][4];                                           \
        _Pragma("unroll")                                                      \
        for (int mt = 0; mt < 2; mt++) ldm4(a_[mt], aBase[mt] + (ks) * 32);    \
        _Pragma("unroll")                                                      \
        for (int n16 = 0; n16 < 4; n16++) ldm4(b_[n16], bBase[n16] + (ks) * 32); \
        _Pragma("unroll")                                                      \
        for (int mt = 0; mt < 2; mt++)                                         \
            _Pragma("unroll")                                                  \
            for (int nt = 0; nt < 8; nt++)                                     \
                mma_f16(acc[mt][nt], a_[mt], &b_[nt >> 1][(nt & 1) * 2]);      \
    } while (0)

    CP_WAIT(3); __syncthreads();
    KSTEP(0); KSTEP(1);
    CP_WAIT(2); __syncthreads();
    KSTEP(2); KSTEP(3);
    CP_WAIT(1); __syncthreads();
    KSTEP(4); KSTEP(5);
    CP_WAIT(0); __syncthreads();
    KSTEP(6); KSTEP(7);
#undef KSTEP

    // ---- epilogue: exp + row/col sums ----
    const float SC = 20.0f * 1.4426950408889634f;
    bool dt = (ti == tj);
    int g = lid >> 2, tg = lid & 3;

    float rs[2][2] = {{0.f, 0.f}, {0.f, 0.f}};
    float cs[8][2];
#pragma unroll
    for (int nt = 0; nt < 8; nt++) { cs[nt][0] = 0.f; cs[nt][1] = 0.f; }

#pragma unroll
    for (int mt = 0; mt < 2; mt++)
#pragma unroll
        for (int nt = 0; nt < 8; nt++)
#pragma unroll
            for (int r = 0; r < 4; r++) {
                int h2 = r >> 1, c2 = r & 1;
                int lr = wy * 32 + mt * 16 + g + h2 * 8;
                int lc = wx * 64 + nt * 8 + tg * 2 + c2;
                float e = ex2f(fmaf(acc[mt][nt][r], SC, -SC));
                if (type != 0 && dt && lr == lc) e = 0.f;   // mask diag of aa / bb
                rs[mt][h2] += e;
                cs[nt][c2] += e;
            }

    // row sums: reduce over tg (lane bits 0,1)
#pragma unroll
    for (int mt = 0; mt < 2; mt++)
#pragma unroll
        for (int h2 = 0; h2 < 2; h2++) {
            float v = rs[mt][h2];
            v += __shfl_xor_sync(0xffffffffu, v, 1);
            v += __shfl_xor_sync(0xffffffffu, v, 2);
            if (tg == 0) red_r[wx][wy * 32 + mt * 16 + g + h2 * 8] = v;
        }
    // col sums: reduce over g (lane bits 2,3,4)
#pragma unroll
    for (int nt = 0; nt < 8; nt++)
#pragma unroll
        for (int c2 = 0; c2 < 2; c2++) {
            float v = cs[nt][c2];
            v += __shfl_xor_sync(0xffffffffu, v, 4);
            v += __shfl_xor_sync(0xffffffffu, v, 8);
            v += __shfl_xor_sync(0xffffffffu, v, 16);
            if (g == 0) red_c[wy][wx * 64 + nt * 8 + tg * 2 + c2] = v;
        }
    __syncthreads();

    if (t < 128) {
        float s = red_r[0][t] + red_r[1][t];
        atomicAdd((type == 2) ? &g_sb[ib + t] : &g_sa[ib + t], s);
    } else {
        int c = t - 128;
        float s = red_c[0][c] + red_c[1][c] + red_c[2][c] + red_c[3][c];
        if (type == 0) atomicAdd(&g_sb[jb + c], s);          // S_ba rows = S_ab cols
        else if (ti < tj) atomicAdd((type == 1) ? &g_sa[jb + c] : &g_sb[jb + c], s);
    }
}

// ---------------- kernel 3: parallel loss reduction -> out[0] ---------------
__global__ void finalize_partial(float* __restrict__ out) {
    __shared__ float sh[128];
    int t = threadIdx.x;
    int i = blockIdx.x * 128 + t;     // 32 blocks x 128 threads = 4096
    float local = 20.0f
                + 0.34657359027997264f * (__log2f(g_sa[i]) + __log2f(g_sb[i]))
                - g_diag[i];
    sh[t] = local;
    __syncthreads();
    for (int s = 64; s > 0; s >>= 1) {
        if (t < s) sh[t] += sh[t + s];
        __syncthreads();
    }
    if (t == 0) atomicAdd(out, sh[0] * (1.0f / (float)BSZ));
}

extern "C" void kernel_launch(void* const* d_in, const int* in_sizes, int n_in,
                              void* d_out, int out_size) {
    const float* emb = (const float*)d_in[0];
    const int* links = (const int*)d_in[1];
    (void)in_sizes; (void)n_in; (void)out_size;

    cudaFuncSetAttribute(tile_kernel, cudaFuncAttributeMaxDynamicSharedMemorySize, SMEM_DYN);

    gather_norm<<<512, 256>>>(emb, links, (float*)d_out);
    tile_kernel<<<N_TILES, 256, SMEM_DYN>>>();
    finalize_partial<<<32, 128>>>((float*)d_out);
}

// round 15
// speedup vs baseline: 1.0783x; 1.0783x over previous
#include <cuda_runtime.h>
#include <cuda_fp16.h>
#include <cstdint>

#define BSZ 4096
#define DIM 128
#define NT  32   // 4096 / 128 tiles per dimension
#define N_AB   (NT * NT)            // 1024 full ab tiles
#define N_TRI  (NT * (NT + 1) / 2)  // 528 upper-triangle tiles
#define N_TILES (N_AB + 2 * N_TRI)  // 2080

// ---------------- scratch (device globals; no runtime allocation) -----------
__device__ __align__(256) __half g_Zi_h[BSZ * DIM];   // fp16 normalized rows (links[:,0])
__device__ __align__(256) __half g_Zj_h[BSZ * DIM];   // fp16 normalized rows (links[:,1])
__device__ float g_sa[BSZ];     // sum exp(logit-20) rows of logits_a
__device__ float g_sb[BSZ];     // sum exp(logit-20) rows of logits_b
__device__ float g_diag[BSZ];   // logits_ab[i,i] (exact fp32)

__device__ __forceinline__ float ex2f(float x) {
    float y;
    asm("ex2.approx.ftz.f32 %0, %1;" : "=f"(y) : "f"(x));
    return y;
}

__device__ __forceinline__ uint32_t smem_u32(const void* p) {
    uint32_t a;
    asm("{ .reg .u64 t; cvta.to.shared.u64 t, %1; cvt.u32.u64 %0, t; }" : "=r"(a) : "l"(p));
    return a;
}

__device__ __forceinline__ void cp16(uint32_t dst, const void* src) {
    asm volatile("cp.async.cg.shared.global [%0], [%1], 16;" :: "r"(dst), "l"(src) : "memory");
}
#define CP_COMMIT() asm volatile("cp.async.commit_group;" ::: "memory")
#define CP_WAIT(n)  asm volatile("cp.async.wait_group %0;" :: "n"(n) : "memory")

__device__ __forceinline__ void ldm4(uint32_t* r, uint32_t addr) {
    asm volatile("ldmatrix.sync.aligned.m8n8.x4.shared.b16 {%0,%1,%2,%3}, [%4];"
                 : "=r"(r[0]), "=r"(r[1]), "=r"(r[2]), "=r"(r[3]) : "r"(addr));
}

__device__ __forceinline__ void mma_f16(float* d, const uint32_t* a, const uint32_t* b) {
    asm volatile("mma.sync.aligned.m16n8k16.row.col.f32.f16.f16.f32 "
                 "{%0,%1,%2,%3}, {%4,%5,%6,%7}, {%8,%9}, {%0,%1,%2,%3};"
                 : "+f"(d[0]), "+f"(d[1]), "+f"(d[2]), "+f"(d[3])
                 : "r"(a[0]), "r"(a[1]), "r"(a[2]), "r"(a[3]), "r"(b[0]), "r"(b[1]));
}

// ---------------- kernel 1: gather + normalize + fp16 store + exact diag ----
// One warp per link row; each thread loads Zi and Zj chunks (MLP=2), three
// shfl reductions give both norms and the exact diag dot. No smem.
__global__ void gather_norm(const float* __restrict__ emb,
                            const int* __restrict__ links32,
                            float* __restrict__ out) {
    int tid  = blockIdx.x * blockDim.x + threadIdx.x;
    if (tid < BSZ) { g_sa[tid] = 0.f; g_sb[tid] = 0.f; }
    if (tid == 0) out[0] = 0.f;      // accumulated by finalize_partial

    int lane = threadIdx.x & 31;
    int row  = tid >> 5;             // link row 0..4095 (grid = 512 x 256)

    // dtype sniff: int64 links have all-zero odd 32-bit words (values < 2e5)
    bool is64 = true;
#pragma unroll
    for (int j = 0; j < 16; j++) is64 &= (__ldg(&links32[2 * j + 1]) == 0);

    long long si, sj;
    if (is64) {
        si = reinterpret_cast<const long long*>(links32)[2 * row];
        sj = reinterpret_cast<const long long*>(links32)[2 * row + 1];
    } else {
        si = (long long)links32[2 * row];
        sj = (long long)links32[2 * row + 1];
    }

    float4 a = reinterpret_cast<const float4*>(emb + (size_t)si * DIM)[lane];
    float4 b = reinterpret_cast<const float4*>(emb + (size_t)sj * DIM)[lane];

    float ssA = a.x * a.x + a.y * a.y + a.z * a.z + a.w * a.w;
    float ssB = b.x * b.x + b.y * b.y + b.z * b.z + b.w * b.w;
    float dab = a.x * b.x + a.y * b.y + a.z * b.z + a.w * b.w;
#pragma unroll
    for (int o = 16; o; o >>= 1) {
        ssA += __shfl_xor_sync(0xffffffffu, ssA, o);
        ssB += __shfl_xor_sync(0xffffffffu, ssB, o);
        dab += __shfl_xor_sync(0xffffffffu, dab, o);
    }
    float invA = 1.0f / fmaxf(sqrtf(ssA), 1e-12f);
    float invB = 1.0f / fmaxf(sqrtf(ssB), 1e-12f);

    __half2 ha0; ha0.x = __float2half_rn(a.x * invA); ha0.y = __float2half_rn(a.y * invA);
    __half2 ha1; ha1.x = __float2half_rn(a.z * invA); ha1.y = __float2half_rn(a.w * invA);
    __half2 hb0; hb0.x = __float2half_rn(b.x * invB); hb0.y = __float2half_rn(b.y * invB);
    __half2 hb1; hb1.x = __float2half_rn(b.z * invB); hb1.y = __float2half_rn(b.w * invB);
    __half* di = g_Zi_h + row * DIM + lane * 4;
    __half* dj = g_Zj_h + row * DIM + lane * 4;
    reinterpret_cast<__half2*>(di)[0] = ha0;
    reinterpret_cast<__half2*>(di)[1] = ha1;
    reinterpret_cast<__half2*>(dj)[0] = hb0;
    reinterpret_cast<__half2*>(dj)[1] = hb1;

    if (lane == 0) g_diag[row] = dab * invA * invB * 20.0f;
}

// ---------------- kernel 2: fp16 mma.sync Gram tile + fused epilogue --------
// 256 threads = 8 warps in a 4x2 grid; warp tile 32 rows x 64 cols.
// smem: 2 tiles [A | B], 128 rows x 128 fp16, rows padded to 272B.
// Tile loads split in TWO cp.async K-half groups (measured optimum): the
// second half streams in under the first half's MMAs.
#define PB    272            // bytes per smem row
#define BUFB  (128 * PB)     // 34816 bytes per buffer
#define SMEM_DYN (2 * BUFB)  // 69632

__global__ __launch_bounds__(256, 2) void tile_kernel() {
    // Dense tile id -> (type, ti, tj). [0,1024): ab full; then two triangles.
    int bid = blockIdx.x;
    int type, ti, tj;
    if (bid < N_AB) {
        type = 0; ti = bid >> 5; tj = bid & 31;
    } else {
        int idx = bid - N_AB;
        type = 1 + (idx >= N_TRI);
        if (idx >= N_TRI) idx -= N_TRI;
        int i = (int)((65.0f - sqrtf(4225.0f - 8.0f * (float)idx)) * 0.5f);
        while (i > 0 && (i * NT - i * (i - 1) / 2) > idx) i--;
        while ((i + 1) * NT - (i + 1) * i / 2 <= idx) i++;
        ti = i;
        tj = i + (idx - (i * NT - i * (i - 1) / 2));
    }

    extern __shared__ char smem[];
    __shared__ float red_r[2][128];
    __shared__ float red_c[4][128];

    const __half *A_g, *B_g;
    A_g = (type == 2) ? g_Zj_h : g_Zi_h;
    B_g = (type == 0) ? g_Zj_h : A_g;

    const int ib = ti * 128, jb = tj * 128;
    const uint32_t sb = smem_u32(smem);
    int t = threadIdx.x;
    int wid = t >> 5, lid = t & 31;
    int wy = wid & 3, wx = wid >> 2;   // warp tile: rows wy*32..+32, cols wx*64..+64

    // ---- K-split cp.async load: half h covers ch h*8..h*8+7 (ks 4h..4h+3) --
#pragma unroll
    for (int h = 0; h < 2; h++) {
#pragma unroll
        for (int i = 0; i < 4; i++) {
            int idx = t + 256 * i;          // 0..1023 per half
            int row = idx >> 3, chh = idx & 7;
            int ch  = h * 8 + chh;
            uint32_t doff = (uint32_t)(row * PB + ch * 16);
            cp16(sb + doff,        A_g + (size_t)(ib + row) * DIM + ch * 8);
            cp16(sb + BUFB + doff, B_g + (size_t)(jb + row) * DIM + ch * 8);
        }
        CP_COMMIT();
    }

    // ---- ldmatrix base addresses (k-invariant parts) ----
    int rowA = lid & 15, ca = lid >> 4;
    int rowB = (lid & 7) | ((lid >> 1) & 8);
    int cb   = (lid >> 3) & 1;

    uint32_t aBase[2], bBase[4];
#pragma unroll
    for (int mt = 0; mt < 2; mt++)
        aBase[mt] = sb + (uint32_t)((wy * 32 + mt * 16 + rowA) * PB + ca * 16);
#pragma unroll
    for (int n16 = 0; n16 < 4; n16++)
        bBase[n16] = sb + BUFB + (uint32_t)((wx * 64 + n16 * 16 + rowB) * PB + cb * 16);

    float acc[2][8][4];
#pragma unroll
    for (int mt = 0; mt < 2; mt++)
#pragma unroll
        for (int nt = 0; nt < 8; nt++)
#pragma unroll
            for (int r = 0; r < 4; r++) acc[mt][nt][r] = 0.f;

    // ---- compute in two halves; half 1 overlaps half 2's copies ----
    CP_WAIT(1);          // first commit group complete
    __syncthreads();
#pragma unroll
    for (int ks = 0; ks < 4; ks++) {
        uint32_t a[2][4], b[4][4];
#pragma unroll
        for (int mt = 0; mt < 2; mt++) ldm4(a[mt], aBase[mt] + ks * 32);
#pragma unroll
        for (int n16 = 0; n16 < 4; n16++) ldm4(b[n16], bBase[n16] + ks * 32);
#pragma unroll
        for (int mt = 0; mt < 2; mt++)
#pragma unroll
            for (int nt = 0; nt < 8; nt++)
                mma_f16(acc[mt][nt], a[mt], &b[nt >> 1][(nt & 1) * 2]);
    }
    CP_WAIT(0);          // second half complete
    __syncthreads();
#pragma unroll
    for (int ks = 4; ks < 8; ks++) {
        uint32_t a[2][4], b[4][4];
#pragma unroll
        for (int mt = 0; mt < 2; mt++) ldm4(a[mt], aBase[mt] + ks * 32);
#pragma unroll
        for (int n16 = 0; n16 < 4; n16++) ldm4(b[n16], bBase[n16] + ks * 32);
#pragma unroll
        for (int mt = 0; mt < 2; mt++)
#pragma unroll
            for (int nt = 0; nt < 8; nt++)
                mma_f16(acc[mt][nt], a[mt], &b[nt >> 1][(nt & 1) * 2]);
    }

    // ---- epilogue: exp + row/col sums ----
    const float SC = 20.0f * 1.4426950408889634f;
    bool dt = (ti == tj);
    int g = lid >> 2, tg = lid & 3;

    float rs[2][2] = {{0.f, 0.f}, {0.f, 0.f}};
    float cs[8][2];
#pragma unroll
    for (int nt = 0; nt < 8; nt++) { cs[nt][0] = 0.f; cs[nt][1] = 0.f; }

#pragma unroll
    for (int mt = 0; mt < 2; mt++)
#pragma unroll
        for (int nt = 0; nt < 8; nt++)
#pragma unroll
            for (int r = 0; r < 4; r++) {
                int h2 = r >> 1, c2 = r & 1;
                int lr = wy * 32 + mt * 16 + g + h2 * 8;
                int lc = wx * 64 + nt * 8 + tg * 2 + c2;
                float e = ex2f(fmaf(acc[mt][nt][r], SC, -SC));
                if (type != 0 && dt && lr == lc) e = 0.f;   // mask diag of aa / bb
                rs[mt][h2] += e;
                cs[nt][c2] += e;
            }

    // row sums: reduce over tg (lane bits 0,1)
#pragma unroll
    for (int mt = 0; mt < 2; mt++)
#pragma unroll
        for (int h2 = 0; h2 < 2; h2++) {
            float v = rs[mt][h2];
            v += __shfl_xor_sync(0xffffffffu, v, 1);
            v += __shfl_xor_sync(0xffffffffu, v, 2);
            if (tg == 0) red_r[wx][wy * 32 + mt * 16 + g + h2 * 8] = v;
        }
    // col sums: reduce over g (lane bits 2,3,4)
#pragma unroll
    for (int nt = 0; nt < 8; nt++)
#pragma unroll
        for (int c2 = 0; c2 < 2; c2++) {
            float v = cs[nt][c2];
            v += __shfl_xor_sync(0xffffffffu, v, 4);
            v += __shfl_xor_sync(0xffffffffu, v, 8);
            v += __shfl_xor_sync(0xffffffffu, v, 16);
            if (g == 0) red_c[wy][wx * 64 + nt * 8 + tg * 2 + c2] = v;
        }
    __syncthreads();

    if (t < 128) {
        float s = red_r[0][t] + red_r[1][t];
        atomicAdd((type == 2) ? &g_sb[ib + t] : &g_sa[ib + t], s);
    } else {
        int c = t - 128;
        float s = red_c[0][c] + red_c[1][c] + red_c[2][c] + red_c[3][c];
        if (type == 0) atomicAdd(&g_sb[jb + c], s);          // S_ba rows = S_ab cols
        else if (ti < tj) atomicAdd((type == 1) ? &g_sa[jb + c] : &g_sb[jb + c], s);
    }
}

// ---------------- kernel 3: parallel loss reduction -> out[0] ---------------
__global__ void finalize_partial(float* __restrict__ out) {
    __shared__ float sh[128];
    int t = threadIdx.x;
    int i = blockIdx.x * 128 + t;     // 32 blocks x 128 threads = 4096
    float local = 20.0f
                + 0.34657359027997264f * (__log2f(g_sa[i]) + __log2f(g_sb[i]))
                - g_diag[i];
    sh[t] = local;
    __syncthreads();
    for (int s = 64; s > 0; s >>= 1) {
        if (t < s) sh[t] += sh[t + s];
        __syncthreads();
    }
    if (t == 0) atomicAdd(out, sh[0] * (1.0f / (float)BSZ));
}

extern "C" void kernel_launch(void* const* d_in, const int* in_sizes, int n_in,
                              void* d_out, int out_size) {
    const float* emb = (const float*)d_in[0];
    const int* links = (const int*)d_in[1];
    (void)in_sizes; (void)n_in; (void)out_size;

    cudaFuncSetAttribute(tile_kernel, cudaFuncAttributeMaxDynamicSharedMemorySize, SMEM_DYN);

    gather_norm<<<512, 256>>>(emb, links, (float*)d_out);
    tile_kernel<<<N_TILES, 256, SMEM_DYN>>>();
    finalize_partial<<<32, 128>>>((float*)d_out);
}